// round 1
// baseline (speedup 1.0000x reference)
#include <cuda_runtime.h>
#include <math.h>

#define FHH 32
#define FWW 88
#define NPIX 2816          // 32*88
#define NCAM 6
#define FCH 256            // conv channels
#define COUT 128           // BEV channels
#define ND 59              // depth bins
#define NVOX 16384         // 128*128 BEV cells

// ---------------- scratch (static device allocations) ----------------
__device__ __align__(16) float g_h1[NCAM * FCH * NPIX];
__device__ __align__(16) float g_h2[NCAM * FCH * NPIX];
__device__ __align__(16) float g_feat[NCAM * COUT * NPIX];
__device__ __align__(16) float g_w1t[9 * FCH * FCH];
__device__ __align__(16) float g_w2t[9 * FCH * FCH];
__device__ __align__(16) float g_w3t[FCH * COUT];
__device__ float g_scale1[FCH], g_scale2[FCH];
__device__ float g_beta1[FCH], g_beta2[FCH], g_beta3[COUT];
__device__ __align__(16) float g_bev[NVOX * COUT];   // [vox][c] channel-contiguous

// ---------------- setup: fold BN into scale/beta ----------------
__global__ void setup_kernel(const float* __restrict__ c1b,
                             const float* __restrict__ g1, const float* __restrict__ b1,
                             const float* __restrict__ m1, const float* __restrict__ v1,
                             const float* __restrict__ c2b,
                             const float* __restrict__ g2, const float* __restrict__ b2,
                             const float* __restrict__ m2, const float* __restrict__ v2,
                             const float* __restrict__ c3b)
{
    int i = threadIdx.x;
    if (i < FCH) {
        float s1 = g1[i] * rsqrtf(v1[i] + 1e-3f);
        g_scale1[i] = s1;
        g_beta1[i] = (c1b[i] - m1[i]) * s1 + b1[i];
        float s2 = g2[i] * rsqrtf(v2[i] + 1e-3f);
        g_scale2[i] = s2;
        g_beta2[i] = (c2b[i] - m2[i]) * s2 + b2[i];
    }
    if (i < COUT) g_beta3[i] = c3b[i];
}

// ---------------- weight transforms: (Co,Ci,3,3)->[t][ci][co], scale folded ----------------
__global__ void wtrans3x3_kernel(const float* __restrict__ w,
                                 const float* __restrict__ scale,
                                 float* __restrict__ out)
{
    int idx = blockIdx.x * blockDim.x + threadIdx.x;   // over 9*256*256, co fastest
    if (idx >= 9 * FCH * FCH) return;
    int t  = idx / (FCH * FCH);
    int r  = idx % (FCH * FCH);
    int ci = r / FCH;
    int co = r % FCH;
    out[idx] = w[(co * FCH + ci) * 9 + t] * scale[co];
}

__global__ void wtrans1x1_kernel(const float* __restrict__ w, float* __restrict__ out)
{
    int idx = blockIdx.x * blockDim.x + threadIdx.x;   // over 256*128, co fastest
    if (idx >= FCH * COUT) return;
    int ci = idx / COUT;
    int co = idx % COUT;
    out[idx] = w[co * FCH + ci];
}

// ---------------- implicit-GEMM conv, BN/bias/relu fused in epilogue ----------------
// Tile: BM=128 (co) x BN=128 (pixels), BK=16, 256 threads, 8x8 per-thread micro-tile.
template <int TAPS, bool RELU>
__global__ void __launch_bounds__(256, 2)
conv_kernel(const float* __restrict__ in_all, const float* __restrict__ wtt,
            const float* __restrict__ beta, float* __restrict__ out_all,
            int Cin, int Cout)
{
    const int n   = blockIdx.z;
    const float* in  = in_all + (size_t)n * Cin * NPIX;
    float*       out = out_all + (size_t)n * Cout * NPIX;
    const int co0 = blockIdx.y * 128;
    const int p0  = blockIdx.x * 128;
    const int tid = threadIdx.x;
    const int tm  = tid >> 4;      // 0..15
    const int tn  = tid & 15;      // 0..15

    __shared__ __align__(16) float As[16][128];
    __shared__ __align__(16) float Bs[16][128];

    float acc[8][8];
#pragma unroll
    for (int i = 0; i < 8; i++)
#pragma unroll
        for (int j = 0; j < 8; j++) acc[i][j] = 0.f;

    const int pnB = tid & 127;     // pixel column this thread fills in Bs
    const int kkB = tid >> 7;      // 0 or 1
    const int p  = p0 + pnB;
    const int hh = p / FWW;
    const int ww = p % FWW;

    for (int t = 0; t < TAPS; ++t) {
        bool valid;
        int srcoff;
        if (TAPS == 9) {
            int dy = t / 3 - 1, dx = t % 3 - 1;
            int h2 = hh + dy, w2 = ww + dx;
            valid = (h2 >= 0) && (h2 < FHH) && (w2 >= 0) && (w2 < FWW);
            srcoff = h2 * FWW + w2;
        } else {
            valid = true;
            srcoff = p;
        }
        const float* wt = wtt + (size_t)t * Cin * Cout;

        for (int k0 = 0; k0 < Cin; k0 += 16) {
            // A tile: 16 x 128 coalesced float4 loads (weights pre-transposed, co fastest)
#pragma unroll
            for (int i = 0; i < 2; i++) {
                int idx = tid + i * 256;           // 0..511
                int kk = idx >> 5;                 // 0..15
                int c4 = idx & 31;                 // 0..31
                ((float4*)As)[kk * 32 + c4] =
                    *(const float4*)(wt + (size_t)(k0 + kk) * Cout + co0 + c4 * 4);
            }
            // B tile: implicit-im2col with zero padding
#pragma unroll
            for (int i = 0; i < 8; i++) {
                int kk = kkB + i * 2;
                Bs[kk][pnB] = valid ? in[(size_t)(k0 + kk) * NPIX + srcoff] : 0.f;
            }
            __syncthreads();
#pragma unroll
            for (int kk = 0; kk < 16; kk++) {
                float4 a0 = *(const float4*)&As[kk][tm * 8];
                float4 a1 = *(const float4*)&As[kk][tm * 8 + 4];
                float4 b0 = *(const float4*)&Bs[kk][tn * 8];
                float4 b1 = *(const float4*)&Bs[kk][tn * 8 + 4];
                float a[8] = {a0.x, a0.y, a0.z, a0.w, a1.x, a1.y, a1.z, a1.w};
                float b[8] = {b0.x, b0.y, b0.z, b0.w, b1.x, b1.y, b1.z, b1.w};
#pragma unroll
                for (int i = 0; i < 8; i++)
#pragma unroll
                    for (int j = 0; j < 8; j++) acc[i][j] += a[i] * b[j];
            }
            __syncthreads();
        }
    }

#pragma unroll
    for (int i = 0; i < 8; i++) {
        int co = co0 + tm * 8 + i;
        float be = beta[co];
        float* orow = out + (size_t)co * NPIX + p0 + tn * 8;
#pragma unroll
        for (int j = 0; j < 8; j++) {
            float v = acc[i][j] + be;
            if (RELU) v = fmaxf(v, 0.f);
            orow[j] = v;
        }
    }
}

// ---------------- zero the scratch BEV ----------------
__global__ void zero_bev_kernel()
{
    int idx = blockIdx.x * blockDim.x + threadIdx.x;
    float4 z = make_float4(0.f, 0.f, 0.f, 0.f);
    for (int i = idx; i < NVOX * COUT / 4; i += gridDim.x * blockDim.x)
        ((float4*)g_bev)[i] = z;
}

// ---------------- fused depth-softmax + lift + splat ----------------
// One block per (cam, pixel). 128 threads. float4 RED into channel-contiguous BEV.
__global__ void __launch_bounds__(128)
splat_kernel(const float* __restrict__ rel, const int* __restrict__ vox,
             const float* __restrict__ log_scale, const float* __restrict__ shift,
             const float* __restrict__ log_sigma, const float* __restrict__ feat)
{
    const int pb = blockIdx.x;             // 0 .. NCAM*NPIX-1
    const int n = pb / NPIX;
    const int p = pb % NPIX;
    const int tid = threadIdx.x;

    __shared__ float sw[ND];
    __shared__ int   sv[ND];
    __shared__ __align__(16) float sf[COUT];
    __shared__ float s_mx, s_inv;

    const float metric = fminf(fmaxf(expf(log_scale[0]) * rel[n * NPIX + p] + shift[0], 0.5f), 150.f);
    const float sigma  = fminf(fmaxf(expf(log_sigma[0]), 0.1f), 20.f);

    if (tid < ND) {
        sw[tid] = -fabsf(metric - (float)(tid + 1)) / sigma;
        sv[tid] = vox[(size_t)(n * ND + tid) * NPIX + p];
    }
    sf[tid] = feat[(size_t)(n * COUT + tid) * NPIX + p];
    __syncthreads();

    if (tid == 0) {
        float mx = -1e30f;
        for (int d = 0; d < ND; d++) mx = fmaxf(mx, sw[d]);
        float s = 0.f;
        for (int d = 0; d < ND; d++) s += expf(sw[d] - mx);
        s_mx = mx;
        s_inv = 1.f / s;
    }
    __syncthreads();
    if (tid < ND) sw[tid] = expf(sw[tid] - s_mx) * s_inv;
    __syncthreads();

    const int lane = tid & 31;
    const int wid  = tid >> 5;
    float4 f = *(const float4*)&sf[lane * 4];
    for (int d = wid; d < ND; d += 4) {
        float wg = sw[d];
        float4 v = make_float4(wg * f.x, wg * f.y, wg * f.z, wg * f.w);
        atomicAdd((float4*)&g_bev[(size_t)sv[d] * COUT + lane * 4], v);   // RED.128 (sm_90+)
    }
}

// ---------------- transpose [vox][c] -> output (C, X*Y) ----------------
__global__ void transpose_kernel(float* __restrict__ out)
{
    __shared__ float tile[32][33];
    int v0 = blockIdx.x * 32;
    int c0 = blockIdx.y * 32;
    int tx = threadIdx.x;
    int ty = threadIdx.y;
#pragma unroll
    for (int i = 0; i < 32; i += 8)
        tile[ty + i][tx] = g_bev[(size_t)(v0 + ty + i) * COUT + c0 + tx];
    __syncthreads();
#pragma unroll
    for (int i = 0; i < 32; i += 8)
        out[(size_t)(c0 + ty + i) * NVOX + v0 + tx] = tile[tx][ty + i];
}

// ---------------- launch ----------------
extern "C" void kernel_launch(void* const* d_in, const int* in_sizes, int n_in,
                              void* d_out, int out_size)
{
    const float* rel       = (const float*)d_in[0];
    const float* img       = (const float*)d_in[1];
    const int*   vox       = (const int*)d_in[2];
    const float* log_scale = (const float*)d_in[3];
    const float* shift     = (const float*)d_in[4];
    const float* log_sigma = (const float*)d_in[5];
    const float* w1  = (const float*)d_in[6];
    const float* c1b = (const float*)d_in[7];
    const float* g1  = (const float*)d_in[8];
    const float* b1  = (const float*)d_in[9];
    const float* m1  = (const float*)d_in[10];
    const float* v1  = (const float*)d_in[11];
    const float* w2  = (const float*)d_in[12];
    const float* c2b = (const float*)d_in[13];
    const float* g2  = (const float*)d_in[14];
    const float* b2  = (const float*)d_in[15];
    const float* m2  = (const float*)d_in[16];
    const float* v2  = (const float*)d_in[17];
    const float* w3  = (const float*)d_in[18];
    const float* c3b = (const float*)d_in[19];
    float* out = (float*)d_out;

    // device symbol addresses (query only; no allocation)
    float *h1p, *h2p, *featp, *w1tp, *w2tp, *w3tp, *sc1p, *sc2p, *be1p, *be2p, *be3p;
    cudaGetSymbolAddress((void**)&h1p,   g_h1);
    cudaGetSymbolAddress((void**)&h2p,   g_h2);
    cudaGetSymbolAddress((void**)&featp, g_feat);
    cudaGetSymbolAddress((void**)&w1tp,  g_w1t);
    cudaGetSymbolAddress((void**)&w2tp,  g_w2t);
    cudaGetSymbolAddress((void**)&w3tp,  g_w3t);
    cudaGetSymbolAddress((void**)&sc1p,  g_scale1);
    cudaGetSymbolAddress((void**)&sc2p,  g_scale2);
    cudaGetSymbolAddress((void**)&be1p,  g_beta1);
    cudaGetSymbolAddress((void**)&be2p,  g_beta2);
    cudaGetSymbolAddress((void**)&be3p,  g_beta3);

    setup_kernel<<<1, 256>>>(c1b, g1, b1, m1, v1, c2b, g2, b2, m2, v2, c3b);

    wtrans3x3_kernel<<<(9 * FCH * FCH + 255) / 256, 256>>>(w1, sc1p, w1tp);
    wtrans3x3_kernel<<<(9 * FCH * FCH + 255) / 256, 256>>>(w2, sc2p, w2tp);
    wtrans1x1_kernel<<<(FCH * COUT + 255) / 256, 256>>>(w3, w3tp);

    zero_bev_kernel<<<2048, 256>>>();

    dim3 cgrid(NPIX / 128, FCH / 128, NCAM);     // (22, 2, 6)
    conv_kernel<9, true><<<cgrid, 256>>>(img, w1tp, be1p, h1p, FCH, FCH);
    conv_kernel<9, true><<<cgrid, 256>>>(h1p, w2tp, be2p, h2p, FCH, FCH);

    dim3 cgrid3(NPIX / 128, COUT / 128, NCAM);   // (22, 1, 6)
    conv_kernel<1, false><<<cgrid3, 256>>>(h2p, w3tp, be3p, featp, FCH, COUT);

    splat_kernel<<<NCAM * NPIX, 128>>>(rel, vox, log_scale, shift, log_sigma, featp);

    transpose_kernel<<<dim3(NVOX / 32, COUT / 32), dim3(32, 8)>>>(out);
}

// round 2
// speedup vs baseline: 2.1968x; 2.1968x over previous
#include <cuda_runtime.h>
#include <math.h>

#define FHH 32
#define FWW 88
#define NPIX 2816          // 32*88
#define NCAM 6
#define FCH 256            // conv channels
#define COUT 128           // BEV channels
#define ND 59              // depth bins
#define NVOX 16384         // 128*128 BEV cells

// ---------------- scratch (static device allocations) ----------------
__device__ __align__(16) float g_h1[NCAM * FCH * NPIX];
__device__ __align__(16) float g_h2[NCAM * FCH * NPIX];
__device__ __align__(16) float g_feat[NCAM * COUT * NPIX];
__device__ __align__(16) float g_w1t[9 * FCH * FCH];
__device__ __align__(16) float g_w2t[9 * FCH * FCH];
__device__ __align__(16) float g_w3t[FCH * COUT];
__device__ float g_scale1[FCH], g_scale2[FCH];
__device__ float g_beta1[FCH], g_beta2[FCH], g_beta3[COUT];
__device__ __align__(16) float g_bev[NVOX * COUT];   // [vox][c] channel-contiguous

// ---------------- tf32 helpers ----------------
__device__ __forceinline__ unsigned f2tf32(float x) {
    unsigned r;
    asm("cvt.rna.tf32.f32 %0, %1;" : "=r"(r) : "f"(x));
    return r;
}

__device__ __forceinline__ void mma_tf32(float* d, const unsigned* a, unsigned b0, unsigned b1) {
    asm volatile(
        "mma.sync.aligned.m16n8k8.row.col.f32.tf32.tf32.f32 "
        "{%0,%1,%2,%3}, {%4,%5,%6,%7}, {%8,%9}, {%0,%1,%2,%3};\n"
        : "+f"(d[0]), "+f"(d[1]), "+f"(d[2]), "+f"(d[3])
        : "r"(a[0]), "r"(a[1]), "r"(a[2]), "r"(a[3]), "r"(b0), "r"(b1));
}

// ---------------- setup: fold BN into scale/beta ----------------
__global__ void setup_kernel(const float* __restrict__ c1b,
                             const float* __restrict__ g1, const float* __restrict__ b1,
                             const float* __restrict__ m1, const float* __restrict__ v1,
                             const float* __restrict__ c2b,
                             const float* __restrict__ g2, const float* __restrict__ b2,
                             const float* __restrict__ m2, const float* __restrict__ v2,
                             const float* __restrict__ c3b)
{
    int i = threadIdx.x;
    if (i < FCH) {
        float s1 = g1[i] * rsqrtf(v1[i] + 1e-3f);
        g_scale1[i] = s1;
        g_beta1[i] = (c1b[i] - m1[i]) * s1 + b1[i];
        float s2 = g2[i] * rsqrtf(v2[i] + 1e-3f);
        g_scale2[i] = s2;
        g_beta2[i] = (c2b[i] - m2[i]) * s2 + b2[i];
    }
    if (i < COUT) g_beta3[i] = c3b[i];
}

// ---------------- weight transforms: (Co,Ci,3,3)->[t][ci][co], scale folded, tf32-rounded ----------------
__global__ void wtrans3x3_kernel(const float* __restrict__ w,
                                 const float* __restrict__ scale,
                                 float* __restrict__ out)
{
    int idx = blockIdx.x * blockDim.x + threadIdx.x;   // over 9*256*256, co fastest
    if (idx >= 9 * FCH * FCH) return;
    int t  = idx / (FCH * FCH);
    int r  = idx % (FCH * FCH);
    int ci = r / FCH;
    int co = r % FCH;
    out[idx] = __uint_as_float(f2tf32(w[(co * FCH + ci) * 9 + t] * scale[co]));
}

__global__ void wtrans1x1_kernel(const float* __restrict__ w, float* __restrict__ out)
{
    int idx = blockIdx.x * blockDim.x + threadIdx.x;   // over 256*128, co fastest
    if (idx >= FCH * COUT) return;
    int ci = idx / COUT;
    int co = idx % COUT;
    out[idx] = __uint_as_float(f2tf32(w[co * FCH + ci]));
}

// ---------------- implicit-GEMM conv via tf32 mma.sync, BN/bias/relu fused ----------------
// Tile: BM=128 (co) x BN=128 (pixels), BK=32, 256 threads (8 warps, 2x4),
// warp tile 64x32 = 4x4 m16n8k8 mmas per k8-step.
template <int TAPS, bool RELU>
__global__ void __launch_bounds__(256, 2)
conv_kernel(const float* __restrict__ in_all, const float* __restrict__ wtt,
            const float* __restrict__ beta, float* __restrict__ out_all,
            int Cin, int Cout)
{
    const int n   = blockIdx.z;
    const float* in  = in_all + (size_t)n * Cin * NPIX;
    float*       out = out_all + (size_t)n * Cout * NPIX;
    const int co0 = blockIdx.y * 128;
    const int p0  = blockIdx.x * 128;
    const int tid = threadIdx.x;
    const int lane = tid & 31;
    const int wid  = tid >> 5;
    const int wm0 = (wid & 1) * 64;    // warp row offset within 128
    const int wn0 = (wid >> 1) * 32;   // warp col offset within 128

    __shared__ __align__(16) float As[32][132];
    __shared__ __align__(16) float Bs[32][132];

    float acc[4][4][4];
#pragma unroll
    for (int mi = 0; mi < 4; mi++)
#pragma unroll
        for (int ni = 0; ni < 4; ni++)
#pragma unroll
            for (int r = 0; r < 4; r++) acc[mi][ni][r] = 0.f;

    // B loader geometry: fixed pixel column per thread, 16 k-rows
    const int pnB = tid & 127;
    const int kkB = tid >> 7;          // 0 or 1
    const int p  = p0 + pnB;
    const int hh = p / FWW;
    const int ww = p % FWW;

    for (int t = 0; t < TAPS; ++t) {
        bool valid;
        int srcoff;
        if (TAPS == 9) {
            int dy = t / 3 - 1, dx = t % 3 - 1;
            int h2 = hh + dy, w2 = ww + dx;
            valid = (h2 >= 0) && (h2 < FHH) && (w2 >= 0) && (w2 < FWW);
            srcoff = h2 * FWW + w2;
        } else {
            valid = true;
            srcoff = p;
        }
        const float* wt = wtt + (size_t)t * Cin * Cout;

        for (int k0 = 0; k0 < Cin; k0 += 32) {
            // A tile: 32 x 128, coalesced float4 (weights pre-transposed+tf32-rounded)
#pragma unroll
            for (int i = 0; i < 4; i++) {
                int idx = tid + i * 256;           // 0..1023
                int kk = idx >> 5;                 // 0..31
                int c4 = idx & 31;                 // 0..31
                *(float4*)&As[kk][c4 * 4] =
                    *(const float4*)(wt + (size_t)(k0 + kk) * Cout + co0 + c4 * 4);
            }
            // B tile: implicit-im2col with zero padding, tf32-rounded
#pragma unroll
            for (int i = 0; i < 16; i++) {
                int kk = kkB + i * 2;
                float v = valid ? in[(size_t)(k0 + kk) * NPIX + srcoff] : 0.f;
                Bs[kk][pnB] = __uint_as_float(f2tf32(v));
            }
            __syncthreads();

#pragma unroll
            for (int ks = 0; ks < 4; ks++) {
                const int kb = ks * 8;
                const int kq = kb + (lane & 3);
                unsigned a[4][4];
#pragma unroll
                for (int mi = 0; mi < 4; mi++) {
                    int m = wm0 + mi * 16 + (lane >> 2);
                    a[mi][0] = __float_as_uint(As[kq][m]);
                    a[mi][1] = __float_as_uint(As[kq][m + 8]);
                    a[mi][2] = __float_as_uint(As[kq + 4][m]);
                    a[mi][3] = __float_as_uint(As[kq + 4][m + 8]);
                }
#pragma unroll
                for (int ni = 0; ni < 4; ni++) {
                    int nn = wn0 + ni * 8 + (lane >> 2);
                    unsigned b0 = __float_as_uint(Bs[kq][nn]);
                    unsigned b1 = __float_as_uint(Bs[kq + 4][nn]);
#pragma unroll
                    for (int mi = 0; mi < 4; mi++)
                        mma_tf32(acc[mi][ni], a[mi], b0, b1);
                }
            }
            __syncthreads();
        }
    }

    // epilogue: +beta, relu, float2 stores
#pragma unroll
    for (int mi = 0; mi < 4; mi++) {
        int r0 = co0 + wm0 + mi * 16 + (lane >> 2);
        int r1 = r0 + 8;
        float be0 = beta[r0];
        float be1 = beta[r1];
#pragma unroll
        for (int ni = 0; ni < 4; ni++) {
            int c = p0 + wn0 + ni * 8 + (lane & 3) * 2;
            float v0 = acc[mi][ni][0] + be0;
            float v1 = acc[mi][ni][1] + be0;
            float v2 = acc[mi][ni][2] + be1;
            float v3 = acc[mi][ni][3] + be1;
            if (RELU) {
                v0 = fmaxf(v0, 0.f); v1 = fmaxf(v1, 0.f);
                v2 = fmaxf(v2, 0.f); v3 = fmaxf(v3, 0.f);
            }
            *(float2*)(out + (size_t)r0 * NPIX + c) = make_float2(v0, v1);
            *(float2*)(out + (size_t)r1 * NPIX + c) = make_float2(v2, v3);
        }
    }
}

// ---------------- zero the scratch BEV ----------------
__global__ void zero_bev_kernel()
{
    int idx = blockIdx.x * blockDim.x + threadIdx.x;
    float4 z = make_float4(0.f, 0.f, 0.f, 0.f);
    for (int i = idx; i < NVOX * COUT / 4; i += gridDim.x * blockDim.x)
        ((float4*)g_bev)[i] = z;
}

// ---------------- fused depth-softmax + lift + splat ----------------
__global__ void __launch_bounds__(128)
splat_kernel(const float* __restrict__ rel, const int* __restrict__ vox,
             const float* __restrict__ log_scale, const float* __restrict__ shift,
             const float* __restrict__ log_sigma, const float* __restrict__ feat)
{
    const int pb = blockIdx.x;             // 0 .. NCAM*NPIX-1
    const int n = pb / NPIX;
    const int p = pb % NPIX;
    const int tid = threadIdx.x;

    __shared__ float sw[ND];
    __shared__ int   sv[ND];
    __shared__ __align__(16) float sf[COUT];
    __shared__ float s_mx, s_inv;

    const float metric = fminf(fmaxf(expf(log_scale[0]) * rel[n * NPIX + p] + shift[0], 0.5f), 150.f);
    const float sigma  = fminf(fmaxf(expf(log_sigma[0]), 0.1f), 20.f);

    if (tid < ND) {
        sw[tid] = -fabsf(metric - (float)(tid + 1)) / sigma;
        sv[tid] = vox[(size_t)(n * ND + tid) * NPIX + p];
    }
    sf[tid] = feat[(size_t)(n * COUT + tid) * NPIX + p];
    __syncthreads();

    if (tid == 0) {
        float mx = -1e30f;
        for (int d = 0; d < ND; d++) mx = fmaxf(mx, sw[d]);
        float s = 0.f;
        for (int d = 0; d < ND; d++) s += expf(sw[d] - mx);
        s_mx = mx;
        s_inv = 1.f / s;
    }
    __syncthreads();
    if (tid < ND) sw[tid] = expf(sw[tid] - s_mx) * s_inv;
    __syncthreads();

    const int lane = tid & 31;
    const int wid  = tid >> 5;
    float4 f = *(const float4*)&sf[lane * 4];
    for (int d = wid; d < ND; d += 4) {
        float wg = sw[d];
        float4 v = make_float4(wg * f.x, wg * f.y, wg * f.z, wg * f.w);
        atomicAdd((float4*)&g_bev[(size_t)sv[d] * COUT + lane * 4], v);   // RED.128 (sm_90+)
    }
}

// ---------------- transpose [vox][c] -> output (C, X*Y) ----------------
__global__ void transpose_kernel(float* __restrict__ out)
{
    __shared__ float tile[32][33];
    int v0 = blockIdx.x * 32;
    int c0 = blockIdx.y * 32;
    int tx = threadIdx.x;
    int ty = threadIdx.y;
#pragma unroll
    for (int i = 0; i < 32; i += 8)
        tile[ty + i][tx] = g_bev[(size_t)(v0 + ty + i) * COUT + c0 + tx];
    __syncthreads();
#pragma unroll
    for (int i = 0; i < 32; i += 8)
        out[(size_t)(c0 + ty + i) * NVOX + v0 + tx] = tile[tx][ty + i];
}

// ---------------- launch ----------------
extern "C" void kernel_launch(void* const* d_in, const int* in_sizes, int n_in,
                              void* d_out, int out_size)
{
    const float* rel       = (const float*)d_in[0];
    const float* img       = (const float*)d_in[1];
    const int*   vox       = (const int*)d_in[2];
    const float* log_scale = (const float*)d_in[3];
    const float* shift     = (const float*)d_in[4];
    const float* log_sigma = (const float*)d_in[5];
    const float* w1  = (const float*)d_in[6];
    const float* c1b = (const float*)d_in[7];
    const float* g1  = (const float*)d_in[8];
    const float* b1  = (const float*)d_in[9];
    const float* m1  = (const float*)d_in[10];
    const float* v1  = (const float*)d_in[11];
    const float* w2  = (const float*)d_in[12];
    const float* c2b = (const float*)d_in[13];
    const float* g2  = (const float*)d_in[14];
    const float* b2  = (const float*)d_in[15];
    const float* m2  = (const float*)d_in[16];
    const float* v2  = (const float*)d_in[17];
    const float* w3  = (const float*)d_in[18];
    const float* c3b = (const float*)d_in[19];
    float* out = (float*)d_out;

    float *h1p, *h2p, *featp, *w1tp, *w2tp, *w3tp, *sc1p, *sc2p, *be1p, *be2p, *be3p;
    cudaGetSymbolAddress((void**)&h1p,   g_h1);
    cudaGetSymbolAddress((void**)&h2p,   g_h2);
    cudaGetSymbolAddress((void**)&featp, g_feat);
    cudaGetSymbolAddress((void**)&w1tp,  g_w1t);
    cudaGetSymbolAddress((void**)&w2tp,  g_w2t);
    cudaGetSymbolAddress((void**)&w3tp,  g_w3t);
    cudaGetSymbolAddress((void**)&sc1p,  g_scale1);
    cudaGetSymbolAddress((void**)&sc2p,  g_scale2);
    cudaGetSymbolAddress((void**)&be1p,  g_beta1);
    cudaGetSymbolAddress((void**)&be2p,  g_beta2);
    cudaGetSymbolAddress((void**)&be3p,  g_beta3);

    setup_kernel<<<1, 256>>>(c1b, g1, b1, m1, v1, c2b, g2, b2, m2, v2, c3b);

    wtrans3x3_kernel<<<(9 * FCH * FCH + 255) / 256, 256>>>(w1, sc1p, w1tp);
    wtrans3x3_kernel<<<(9 * FCH * FCH + 255) / 256, 256>>>(w2, sc2p, w2tp);
    wtrans1x1_kernel<<<(FCH * COUT + 255) / 256, 256>>>(w3, w3tp);

    zero_bev_kernel<<<2048, 256>>>();

    dim3 cgrid(NPIX / 128, FCH / 128, NCAM);     // (22, 2, 6)
    conv_kernel<9, true><<<cgrid, 256>>>(img, w1tp, be1p, h1p, FCH, FCH);
    conv_kernel<9, true><<<cgrid, 256>>>(h1p, w2tp, be2p, h2p, FCH, FCH);

    dim3 cgrid3(NPIX / 128, COUT / 128, NCAM);   // (22, 1, 6)
    conv_kernel<1, false><<<cgrid3, 256>>>(h2p, w3tp, be3p, featp, FCH, COUT);

    splat_kernel<<<NCAM * NPIX, 128>>>(rel, vox, log_scale, shift, log_sigma, featp);

    transpose_kernel<<<dim3(NVOX / 32, COUT / 32), dim3(32, 8)>>>(out);
}